// round 15
// baseline (speedup 1.0000x reference)
#include <cuda_runtime.h>

// Problem constants
constexpr int NNODES = 100000;
constexpr int D      = 64;
constexpr int NE     = 1250000;
constexpr int SB     = (NNODES + 1023) / 1024;  // 98 scan blocks
constexpr int GEMM_BLOCKS = (NNODES + 127) / 128;  // 782
constexpr int FILL_BLOCKS = 1266;                  // 782+1266 = 2048 grid
constexpr int HIST_BLOCKS = 2048;
constexpr int BNRED_BLOCKS = 512;

// Split point for layer-boundary pipelining (multiple of 128)
constexpr int SPLIT      = 59904;                 // 468 gemm tiles
constexpr int SPLIT_T    = SPLIT / 128;           // 468
constexpr int AGGA_BLK   = SPLIT / 8;             // 7488  (8 nodes per 256-thr block)
constexpr int AGGB_BLK   = (NNODES - SPLIT) / 8;  // 5012
constexpr int GEMB_BLK   = GEMM_BLOCKS - SPLIT_T; // 314

// ---------------------------------------------------------------------------
// Device scratch
// ---------------------------------------------------------------------------
__device__ float  g_h[NNODES * D];
__device__ float  g_x[NNODES * D];
__device__ float  g_dis[NNODES];
__device__ int    g_cnt[NNODES];
__device__ int    g_rowptr[NNODES + 1];
__device__ int    g_cursor[NNODES];
__device__ int    g_colidx[NE];
__device__ int    g_blocksum[SB];
__device__ double g_sum[D];
__device__ double g_sumsq[D];
__device__ float  g_scale[D];
__device__ float  g_shift[D];
__device__ int    g_is64;
__device__ int    g_bnticket;

// ---------------------------------------------------------------------------
// 0. init
// ---------------------------------------------------------------------------
__global__ void k_init(const int* __restrict__ e) {
    int i = blockIdx.x * blockDim.x + threadIdx.x;
    if (i < NNODES) g_cnt[i] = 0;
    if (i < D) { g_sum[i] = 0.0; g_sumsq[i] = 0.0; }
    if (i == 0) g_bnticket = 0;
    if (blockIdx.x == 0) {
        __shared__ int s_nz;
        if (threadIdx.x == 0) s_nz = 0;
        __syncthreads();
        int nz = 0;
        for (int j = threadIdx.x; j < 2048; j += blockDim.x)
            nz |= (e[2 * j + 1] != 0);
        if (nz) atomicOr(&s_nz, 1);
        __syncthreads();
        if (threadIdx.x == 0) g_is64 = (s_nz == 0) ? 1 : 0;
    }
}

// ---------------------------------------------------------------------------
// Histogram of dst (vectorized 2 edges/iter)
// ---------------------------------------------------------------------------
__global__ void __launch_bounds__(256) k_hist(const void* __restrict__ ep) {
    int i0 = blockIdx.x * 256 + threadIdx.x;
    int stride = HIST_BLOCKS * 256;
    if (g_is64) {
        const longlong2* d2 = (const longlong2*)((const long long*)ep + NE);
        for (int i = i0; i < NE / 2; i += stride) {
            longlong2 v = d2[i];
            atomicAdd(&g_cnt[(int)v.x], 1);
            atomicAdd(&g_cnt[(int)v.y], 1);
        }
    } else {
        const int2* d2 = (const int2*)((const int*)ep + NE);
        for (int i = i0; i < NE / 2; i += stride) {
            int2 v = d2[i];
            atomicAdd(&g_cnt[v.x], 1);
            atomicAdd(&g_cnt[v.y], 1);
        }
    }
}

// ---------------------------------------------------------------------------
// GEMM body (FFMA2): g_h[n] = dis[n] * (X[n] @ W^T)
// ---------------------------------------------------------------------------
__device__ __forceinline__ void gemm_body(const float* __restrict__ X,
                                          const float* __restrict__ W,
                                          int bid) {
    __shared__ float2 sx2[128 * 32];   // sx2[r*32 + ((kp + r) & 31)]
    __shared__ float2 sw2[32 * 64];    // sw2[kp*64 + j*8 + tc]
    int tid = threadIdx.x;

    const float2* W2 = (const float2*)W;
    for (int i = tid; i < 2048; i += 256) {
        int kp = i >> 6, t6 = i & 63;
        int j = t6 >> 3, tcc = t6 & 7;
        int d = tcc * 8 + j;
        sw2[i] = W2[d * 32 + kp];
    }
    int n0 = bid * 128;
    const float4* X4 = (const float4*)X;
    for (int i = tid; i < 2048; i += 256) {
        int r = i >> 4, c = i & 15;
        int n = n0 + r;
        float4 v = (n < NNODES) ? X4[(size_t)n * 16 + c]
                                : make_float4(0.f, 0.f, 0.f, 0.f);
        sx2[r * 32 + ((2 * c + r) & 31)]     = make_float2(v.x, v.y);
        sx2[r * 32 + ((2 * c + 1 + r) & 31)] = make_float2(v.z, v.w);
    }
    __syncthreads();

    int tc = tid & 7, tr = tid >> 3;
    int nb = tr * 4;
    unsigned long long acc[4][8];
#pragma unroll
    for (int i = 0; i < 4; i++)
#pragma unroll
        for (int j = 0; j < 8; j++) acc[i][j] = 0ull;

#pragma unroll 4
    for (int kp = 0; kp < 32; kp++) {
        unsigned long long wv[8];
#pragma unroll
        for (int j = 0; j < 8; j++)
            wv[j] = *(const unsigned long long*)&sw2[kp * 64 + j * 8 + tc];
        unsigned long long xv[4];
#pragma unroll
        for (int i = 0; i < 4; i++) {
            int n = nb + i;
            xv[i] = *(const unsigned long long*)&sx2[n * 32 + ((kp + n) & 31)];
        }
#pragma unroll
        for (int i = 0; i < 4; i++)
#pragma unroll
            for (int j = 0; j < 8; j++)
                asm("fma.rn.f32x2 %0, %1, %2, %0;"
                    : "+l"(acc[i][j]) : "l"(xv[i]), "l"(wv[j]));
    }

#pragma unroll
    for (int i = 0; i < 4; i++) {
        int n = n0 + nb + i;
        if (n < NNODES) {
            float dv = g_dis[n];
            float o[8];
#pragma unroll
            for (int j = 0; j < 8; j++) {
                unsigned long long a = acc[i][j];
                float lo = __uint_as_float((unsigned)(a & 0xffffffffull));
                float hi = __uint_as_float((unsigned)(a >> 32));
                o[j] = (lo + hi) * dv;
            }
            *(float4*)&g_h[(size_t)n * 64 + tc * 8]     = make_float4(o[0], o[1], o[2], o[3]);
            *(float4*)&g_h[(size_t)n * 64 + tc * 8 + 4] = make_float4(o[4], o[5], o[6], o[7]);
        }
    }
}

// CSR fill body (vectorized 2 edges/iter)
__device__ __forceinline__ void fill_body(const void* __restrict__ ep, int fb) {
    int i0 = fb * 256 + threadIdx.x;
    int stride = FILL_BLOCKS * 256;
    if (g_is64) {
        const longlong2* s2 = (const longlong2*)ep;
        const longlong2* d2 = (const longlong2*)((const long long*)ep + NE);
        for (int i = i0; i < NE / 2; i += stride) {
            longlong2 sv = s2[i];
            longlong2 dv = d2[i];
            int p0 = atomicAdd(&g_cursor[(int)dv.x], 1);
            g_colidx[p0] = (int)sv.x;
            int p1 = atomicAdd(&g_cursor[(int)dv.y], 1);
            g_colidx[p1] = (int)sv.y;
        }
    } else {
        const int2* s2 = (const int2*)ep;
        const int2* d2 = (const int2*)((const int*)ep + NE);
        for (int i = i0; i < NE / 2; i += stride) {
            int2 sv = s2[i];
            int2 dv = d2[i];
            int p0 = atomicAdd(&g_cursor[dv.x], 1);
            g_colidx[p0] = sv.x;
            int p1 = atomicAdd(&g_cursor[dv.y], 1);
            g_colidx[p1] = sv.y;
        }
    }
}

// fused: layer-1 GEMM || CSR fill
__global__ void __launch_bounds__(256) k_fused2(const float* __restrict__ X,
                                                 const float* __restrict__ W,
                                                 const void* __restrict__ ep) {
    if (blockIdx.x < GEMM_BLOCKS) gemm_body(X, W, blockIdx.x);
    else                          fill_body(ep, blockIdx.x - GEMM_BLOCKS);
}

// ---------------------------------------------------------------------------
// Parallel scan (2 kernels; proven)
// ---------------------------------------------------------------------------
__global__ void __launch_bounds__(256) k_scan1() {
    __shared__ int warpsum[8];
    int b = blockIdx.x, t = threadIdx.x;
    int base = b * 1024 + t * 4;
    int c[4]; int s = 0;
#pragma unroll
    for (int i = 0; i < 4; i++) {
        int idx = base + i;
        c[i] = (idx < NNODES) ? g_cnt[idx] : 0;
        s += c[i];
    }
    int lane = t & 31, w = t >> 5;
    int v = s;
#pragma unroll
    for (int off = 1; off < 32; off <<= 1) {
        int u = __shfl_up_sync(~0u, v, off);
        if (lane >= off) v += u;
    }
    if (lane == 31) warpsum[w] = v;
    __syncthreads();
    if (t < 8) {
        int u = warpsum[t];
#pragma unroll
        for (int off = 1; off < 8; off <<= 1) {
            int uu = __shfl_up_sync(0xffu, u, off);
            if (t >= off) u += uu;
        }
        warpsum[t] = u;
    }
    __syncthreads();
    int run = v - s + (w > 0 ? warpsum[w - 1] : 0);
#pragma unroll
    for (int i = 0; i < 4; i++) {
        int idx = base + i;
        if (idx < NNODES) g_rowptr[idx] = run;
        run += c[i];
    }
    if (t == 255) g_blocksum[b] = warpsum[7];
}

__global__ void __launch_bounds__(256) k_scan3() {
    __shared__ int red[256];
    int b = blockIdx.x, t = threadIdx.x;
    int bsv = (t < SB) ? g_blocksum[t] : 0;
    red[t] = (t < b) ? bsv : 0;
    __syncthreads();
    for (int off = 128; off > 0; off >>= 1) {
        if (t < off) red[t] += red[t + off];
        __syncthreads();
    }
    int off0 = red[0];
    if (b == SB - 1 && t == 0) g_rowptr[NNODES] = off0 + g_blocksum[SB - 1];
    int base = b * 1024 + t * 4;
#pragma unroll
    for (int i = 0; i < 4; i++) {
        int idx = base + i;
        if (idx < NNODES) {
            int r = g_rowptr[idx] + off0;
            g_rowptr[idx] = r;
            g_cursor[idx] = r;
            g_dis[idx] = rsqrtf((float)(g_cnt[idx] + 1));
        }
    }
}

// ---------------------------------------------------------------------------
// Aggregation body over node range [w0, w1): warp per node, unroll 8
// ---------------------------------------------------------------------------
__device__ __forceinline__ void agg_body(const float* __restrict__ b,
                                         int w0, int w1, int bid) {
    int w = w0 + ((bid * 256 + threadIdx.x) >> 5);
    int l = threadIdx.x & 31;
    if (w >= w1) return;
    const float2* __restrict__ h2 = (const float2*)g_h;
    float dvw = g_dis[w];
    float2 acc = h2[(size_t)w * 32 + l];
    int beg = g_rowptr[w];
    int end = g_rowptr[w + 1];
    int j = beg;
    for (; j + 8 <= end; j += 8) {
        int s[8];
#pragma unroll
        for (int k = 0; k < 8; k++) s[k] = g_colidx[j + k];
        float2 a[8];
#pragma unroll
        for (int k = 0; k < 8; k++) a[k] = h2[(size_t)s[k] * 32 + l];
        float sx0 = (a[0].x + a[1].x) + (a[2].x + a[3].x);
        float sx1 = (a[4].x + a[5].x) + (a[6].x + a[7].x);
        float sy0 = (a[0].y + a[1].y) + (a[2].y + a[3].y);
        float sy1 = (a[4].y + a[5].y) + (a[6].y + a[7].y);
        acc.x += sx0 + sx1;
        acc.y += sy0 + sy1;
    }
    for (; j + 2 <= end; j += 2) {
        int s0 = g_colidx[j], s1 = g_colidx[j + 1];
        float2 a0 = h2[(size_t)s0 * 32 + l];
        float2 a1 = h2[(size_t)s1 * 32 + l];
        acc.x += a0.x + a1.x;
        acc.y += a0.y + a1.y;
    }
    if (j < end) {
        int s = g_colidx[j];
        float2 a = h2[(size_t)s * 32 + l];
        acc.x += a.x; acc.y += a.y;
    }
    float2 bv = ((const float2*)b)[l];
    float2 r;
    r.x = acc.x * dvw + bv.x;
    r.y = acc.y * dvw + bv.y;
    ((float2*)g_x)[(size_t)w * 32 + l] = r;
}

// agg over [0, SPLIT)
__global__ void __launch_bounds__(256) k_aggA(const float* __restrict__ b) {
    agg_body(b, 0, SPLIT, blockIdx.x);
}
// full agg (layer 3)
__global__ void __launch_bounds__(256) k_aggF(const float* __restrict__ b) {
    agg_body(b, 0, NNODES, blockIdx.x);
}
// fused: agg over [SPLIT, NNODES) || gemm_{L+1} tiles [0, SPLIT_T)
__global__ void __launch_bounds__(256) k_aggB_gemmA(const float* __restrict__ b,
                                                     const float* __restrict__ W) {
    if (blockIdx.x < AGGB_BLK) agg_body(b, SPLIT, NNODES, blockIdx.x);
    else                       gemm_body(g_x, W, blockIdx.x - AGGB_BLK);
}
// gemm tiles [SPLIT_T, GEMM_BLOCKS)
__global__ void __launch_bounds__(256) k_gemmB(const float* __restrict__ W) {
    gemm_body(g_x, W, SPLIT_T + blockIdx.x);
}

// ---------------------------------------------------------------------------
// BN column reduction + last-block scale/shift (proven)
// ---------------------------------------------------------------------------
__global__ void __launch_bounds__(256) k_bnred(const float* __restrict__ gamma,
                                               const float* __restrict__ beta) {
    int d  = threadIdx.x & 63;
    int r0 = blockIdx.x * 4 + (threadIdx.x >> 6);
    int rs = gridDim.x * 4;
    float s = 0.f, q = 0.f;
    for (int n = r0; n < NNODES; n += rs) {
        float v = g_x[(size_t)n * 64 + d];
        s += v;
        q += v * v;
    }
    __shared__ double ss[256], sq[256];
    ss[threadIdx.x] = (double)s;
    sq[threadIdx.x] = (double)q;
    __syncthreads();
    if (threadIdx.x < 64) {
        double sd = ss[threadIdx.x] + ss[threadIdx.x + 64] + ss[threadIdx.x + 128] + ss[threadIdx.x + 192];
        double qd = sq[threadIdx.x] + sq[threadIdx.x + 64] + sq[threadIdx.x + 128] + sq[threadIdx.x + 192];
        atomicAdd(&g_sum[d], sd);
        atomicAdd(&g_sumsq[d], qd);
    }
    __shared__ int s_last;
    __threadfence();
    __syncthreads();
    if (threadIdx.x == 0) {
        int t = atomicAdd(&g_bnticket, 1);
        s_last = (t == gridDim.x - 1) ? 1 : 0;
    }
    __syncthreads();
    if (s_last && threadIdx.x < 64) {
        int dd = threadIdx.x;
        double mean = g_sum[dd] / (double)NNODES;
        double var  = g_sumsq[dd] / (double)NNODES - mean * mean;
        double inv  = 1.0 / sqrt(var + 1e-5);
        double sc   = (double)gamma[dd] * inv;
        g_scale[dd] = (float)sc;
        g_shift[dd] = (float)((double)beta[dd] - mean * sc);
    }
}

__global__ void __launch_bounds__(256) k_fin(float* __restrict__ out) {
    int i = blockIdx.x * blockDim.x + threadIdx.x;
    if (i >= NNODES * 16) return;
    float4 v = ((const float4*)g_x)[i];
    int d = (i & 15) * 4;
    v.x = v.x * g_scale[d + 0] + g_shift[d + 0];
    v.y = v.y * g_scale[d + 1] + g_shift[d + 1];
    v.z = v.z * g_scale[d + 2] + g_shift[d + 2];
    v.w = v.w * g_scale[d + 3] + g_shift[d + 3];
    ((float4*)out)[i] = v;
}

// ---------------------------------------------------------------------------
// Launch
// ---------------------------------------------------------------------------
extern "C" void kernel_launch(void* const* d_in, const int* in_sizes, int n_in,
                              void* d_out, int out_size) {
    const float* x     = (const float*)d_in[0];
    const void*  ei    = d_in[1];
    const float* Ws    = (const float*)d_in[2];
    const float* bs    = (const float*)d_in[3];
    const float* gamma = (const float*)d_in[4];
    const float* beta  = (const float*)d_in[5];
    float* out = (float*)d_out;

    k_init<<<(NNODES + 255) / 256, 256>>>((const int*)ei);
    k_hist<<<HIST_BLOCKS, 256>>>(ei);
    k_scan1<<<SB, 256>>>();
    k_scan3<<<SB, 256>>>();
    k_fused2<<<GEMM_BLOCKS + FILL_BLOCKS, 256>>>(x, Ws, ei);

    // layer 1 -> 2 boundary, pipelined
    k_aggA<<<AGGA_BLK, 256>>>(bs);
    k_aggB_gemmA<<<AGGB_BLK + SPLIT_T, 256>>>(bs, Ws + 1 * 64 * 64);
    k_gemmB<<<GEMB_BLK, 256>>>(Ws + 1 * 64 * 64);

    // layer 2 -> 3 boundary, pipelined
    k_aggA<<<AGGA_BLK, 256>>>(bs + 1 * 64);
    k_aggB_gemmA<<<AGGB_BLK + SPLIT_T, 256>>>(bs + 1 * 64, Ws + 2 * 64 * 64);
    k_gemmB<<<GEMB_BLK, 256>>>(Ws + 2 * 64 * 64);

    // layer 3 aggregation (full)
    k_aggF<<<(NNODES * 32) / 256, 256>>>(bs + 2 * 64);

    k_bnred<<<BNRED_BLOCKS, 256>>>(gamma, beta);
    k_fin<<<(NNODES * 16 + 255) / 256, 256>>>(out);
}

// round 16
// speedup vs baseline: 1.1146x; 1.1146x over previous
#include <cuda_runtime.h>

// Problem constants
constexpr int NNODES = 100000;
constexpr int D      = 64;
constexpr int NE     = 1250000;
constexpr int SB     = (NNODES + 1023) / 1024;  // 98 scan blocks
constexpr int GEMM_BLOCKS = (NNODES + 127) / 128;  // 782
constexpr int FILL_BLOCKS = 1266;                  // 782+1266 = 2048 grid
constexpr int HIST_BLOCKS = 2048;
constexpr int BNRED_BLOCKS = 512;

// ---------------------------------------------------------------------------
// Device scratch
// ---------------------------------------------------------------------------
__device__ float  g_h[NNODES * D];
__device__ float  g_x[NNODES * D];
__device__ float  g_dis[NNODES];
__device__ int    g_cnt[NNODES];
__device__ int    g_rowptr[NNODES + 1];
__device__ int    g_cursor[NNODES];
__device__ int    g_colidx[NE];
__device__ int    g_blocksum[SB];
__device__ double g_sum[D];
__device__ double g_sumsq[D];
__device__ float  g_scale[D];
__device__ float  g_shift[D];
__device__ int    g_is64;
__device__ int    g_bnticket;

// ---------------------------------------------------------------------------
// 0. init
// ---------------------------------------------------------------------------
__global__ void k_init(const int* __restrict__ e) {
    int i = blockIdx.x * blockDim.x + threadIdx.x;
    if (i < NNODES) g_cnt[i] = 0;
    if (i < D) { g_sum[i] = 0.0; g_sumsq[i] = 0.0; }
    if (i == 0) g_bnticket = 0;
    if (blockIdx.x == 0) {
        __shared__ int s_nz;
        if (threadIdx.x == 0) s_nz = 0;
        __syncthreads();
        int nz = 0;
        for (int j = threadIdx.x; j < 2048; j += blockDim.x)
            nz |= (e[2 * j + 1] != 0);
        if (nz) atomicOr(&s_nz, 1);
        __syncthreads();
        if (threadIdx.x == 0) g_is64 = (s_nz == 0) ? 1 : 0;
    }
}

// ---------------------------------------------------------------------------
// Histogram of dst (vectorized 2 edges/iter)
// ---------------------------------------------------------------------------
__global__ void __launch_bounds__(256) k_hist(const void* __restrict__ ep) {
    int i0 = blockIdx.x * 256 + threadIdx.x;
    int stride = HIST_BLOCKS * 256;
    if (g_is64) {
        const longlong2* d2 = (const longlong2*)((const long long*)ep + NE);
        for (int i = i0; i < NE / 2; i += stride) {
            longlong2 v = d2[i];
            atomicAdd(&g_cnt[(int)v.x], 1);
            atomicAdd(&g_cnt[(int)v.y], 1);
        }
    } else {
        const int2* d2 = (const int2*)((const int*)ep + NE);
        for (int i = i0; i < NE / 2; i += stride) {
            int2 v = d2[i];
            atomicAdd(&g_cnt[v.x], 1);
            atomicAdd(&g_cnt[v.y], 1);
        }
    }
}

// ---------------------------------------------------------------------------
// GEMM body (FFMA2): g_h[n] = dis[n] * (X[n] @ W^T)
// ---------------------------------------------------------------------------
__device__ __forceinline__ void gemm_body(const float* __restrict__ X,
                                          const float* __restrict__ W,
                                          int bid) {
    __shared__ float2 sx2[128 * 32];   // sx2[r*32 + ((kp + r) & 31)]
    __shared__ float2 sw2[32 * 64];    // sw2[kp*64 + j*8 + tc]
    int tid = threadIdx.x;

    const float2* W2 = (const float2*)W;
    for (int i = tid; i < 2048; i += 256) {
        int kp = i >> 6, t6 = i & 63;
        int j = t6 >> 3, tcc = t6 & 7;
        int d = tcc * 8 + j;
        sw2[i] = W2[d * 32 + kp];
    }
    int n0 = bid * 128;
    const float4* X4 = (const float4*)X;
    for (int i = tid; i < 2048; i += 256) {
        int r = i >> 4, c = i & 15;
        int n = n0 + r;
        float4 v = (n < NNODES) ? X4[(size_t)n * 16 + c]
                                : make_float4(0.f, 0.f, 0.f, 0.f);
        sx2[r * 32 + ((2 * c + r) & 31)]     = make_float2(v.x, v.y);
        sx2[r * 32 + ((2 * c + 1 + r) & 31)] = make_float2(v.z, v.w);
    }
    __syncthreads();

    int tc = tid & 7, tr = tid >> 3;
    int nb = tr * 4;
    unsigned long long acc[4][8];
#pragma unroll
    for (int i = 0; i < 4; i++)
#pragma unroll
        for (int j = 0; j < 8; j++) acc[i][j] = 0ull;

#pragma unroll 4
    for (int kp = 0; kp < 32; kp++) {
        unsigned long long wv[8];
#pragma unroll
        for (int j = 0; j < 8; j++)
            wv[j] = *(const unsigned long long*)&sw2[kp * 64 + j * 8 + tc];
        unsigned long long xv[4];
#pragma unroll
        for (int i = 0; i < 4; i++) {
            int n = nb + i;
            xv[i] = *(const unsigned long long*)&sx2[n * 32 + ((kp + n) & 31)];
        }
#pragma unroll
        for (int i = 0; i < 4; i++)
#pragma unroll
            for (int j = 0; j < 8; j++)
                asm("fma.rn.f32x2 %0, %1, %2, %0;"
                    : "+l"(acc[i][j]) : "l"(xv[i]), "l"(wv[j]));
    }

#pragma unroll
    for (int i = 0; i < 4; i++) {
        int n = n0 + nb + i;
        if (n < NNODES) {
            float dv = g_dis[n];
            float o[8];
#pragma unroll
            for (int j = 0; j < 8; j++) {
                unsigned long long a = acc[i][j];
                float lo = __uint_as_float((unsigned)(a & 0xffffffffull));
                float hi = __uint_as_float((unsigned)(a >> 32));
                o[j] = (lo + hi) * dv;
            }
            *(float4*)&g_h[(size_t)n * 64 + tc * 8]     = make_float4(o[0], o[1], o[2], o[3]);
            *(float4*)&g_h[(size_t)n * 64 + tc * 8 + 4] = make_float4(o[4], o[5], o[6], o[7]);
        }
    }
}

// CSR fill body (vectorized 2 edges/iter)
__device__ __forceinline__ void fill_body(const void* __restrict__ ep, int fb) {
    int i0 = fb * 256 + threadIdx.x;
    int stride = FILL_BLOCKS * 256;
    if (g_is64) {
        const longlong2* s2 = (const longlong2*)ep;
        const longlong2* d2 = (const longlong2*)((const long long*)ep + NE);
        for (int i = i0; i < NE / 2; i += stride) {
            longlong2 sv = s2[i];
            longlong2 dv = d2[i];
            int p0 = atomicAdd(&g_cursor[(int)dv.x], 1);
            g_colidx[p0] = (int)sv.x;
            int p1 = atomicAdd(&g_cursor[(int)dv.y], 1);
            g_colidx[p1] = (int)sv.y;
        }
    } else {
        const int2* s2 = (const int2*)ep;
        const int2* d2 = (const int2*)((const int*)ep + NE);
        for (int i = i0; i < NE / 2; i += stride) {
            int2 sv = s2[i];
            int2 dv = d2[i];
            int p0 = atomicAdd(&g_cursor[dv.x], 1);
            g_colidx[p0] = sv.x;
            int p1 = atomicAdd(&g_cursor[dv.y], 1);
            g_colidx[p1] = sv.y;
        }
    }
}

// fused: layer-1 GEMM (dis-scaled; runs after scan) || CSR fill
__global__ void __launch_bounds__(256) k_fused2(const float* __restrict__ X,
                                                 const float* __restrict__ W,
                                                 const void* __restrict__ ep) {
    if (blockIdx.x < GEMM_BLOCKS) gemm_body(X, W, blockIdx.x);
    else                          fill_body(ep, blockIdx.x - GEMM_BLOCKS);
}

__global__ void __launch_bounds__(256) k_gemm_s(const float* __restrict__ W) {
    gemm_body(g_x, W, blockIdx.x);
}

// ---------------------------------------------------------------------------
// Parallel scan (2 kernels; proven)
// ---------------------------------------------------------------------------
__global__ void __launch_bounds__(256) k_scan1() {
    __shared__ int warpsum[8];
    int b = blockIdx.x, t = threadIdx.x;
    int base = b * 1024 + t * 4;
    int c[4]; int s = 0;
#pragma unroll
    for (int i = 0; i < 4; i++) {
        int idx = base + i;
        c[i] = (idx < NNODES) ? g_cnt[idx] : 0;
        s += c[i];
    }
    int lane = t & 31, w = t >> 5;
    int v = s;
#pragma unroll
    for (int off = 1; off < 32; off <<= 1) {
        int u = __shfl_up_sync(~0u, v, off);
        if (lane >= off) v += u;
    }
    if (lane == 31) warpsum[w] = v;
    __syncthreads();
    if (t < 8) {
        int u = warpsum[t];
#pragma unroll
        for (int off = 1; off < 8; off <<= 1) {
            int uu = __shfl_up_sync(0xffu, u, off);
            if (t >= off) u += uu;
        }
        warpsum[t] = u;
    }
    __syncthreads();
    int run = v - s + (w > 0 ? warpsum[w - 1] : 0);
#pragma unroll
    for (int i = 0; i < 4; i++) {
        int idx = base + i;
        if (idx < NNODES) g_rowptr[idx] = run;
        run += c[i];
    }
    if (t == 255) g_blocksum[b] = warpsum[7];
}

__global__ void __launch_bounds__(256) k_scan3() {
    __shared__ int red[256];
    int b = blockIdx.x, t = threadIdx.x;
    int bsv = (t < SB) ? g_blocksum[t] : 0;
    red[t] = (t < b) ? bsv : 0;
    __syncthreads();
    for (int off = 128; off > 0; off >>= 1) {
        if (t < off) red[t] += red[t + off];
        __syncthreads();
    }
    int off0 = red[0];
    if (b == SB - 1 && t == 0) g_rowptr[NNODES] = off0 + g_blocksum[SB - 1];
    int base = b * 1024 + t * 4;
#pragma unroll
    for (int i = 0; i < 4; i++) {
        int idx = base + i;
        if (idx < NNODES) {
            int r = g_rowptr[idx] + off0;
            g_rowptr[idx] = r;
            g_cursor[idx] = r;
            g_dis[idx] = rsqrtf((float)(g_cnt[idx] + 1));
        }
    }
}

// ---------------------------------------------------------------------------
// Aggregation: warp per node, lane l owns float2 at dim 2l.
// Software-pipelined: next iteration's colidx loads issue before current adds.
// ---------------------------------------------------------------------------
__global__ void __launch_bounds__(256) k_agg(const float* __restrict__ b) {
    int w = (blockIdx.x * blockDim.x + threadIdx.x) >> 5;
    int l = threadIdx.x & 31;
    if (w >= NNODES) return;
    const float2* __restrict__ h2 = (const float2*)g_h;
    float dvw = g_dis[w];
    float2 acc = h2[(size_t)w * 32 + l];
    int beg = g_rowptr[w];
    int end = g_rowptr[w + 1];
    int j = beg;

    int s[8];
    bool have = (j + 8 <= end);
    if (have) {
#pragma unroll
        for (int k = 0; k < 8; k++) s[k] = g_colidx[j + k];
    }
    while (have) {
        // issue gathers for current indices
        float2 a[8];
#pragma unroll
        for (int k = 0; k < 8; k++) a[k] = h2[(size_t)s[k] * 32 + l];
        // prefetch next iteration's indices (overlaps with gather latency)
        int jn = j + 8;
        bool haven = (jn + 8 <= end);
        int sn[8];
        if (haven) {
#pragma unroll
            for (int k = 0; k < 8; k++) sn[k] = g_colidx[jn + k];
        }
        // accumulate current
        float sx0 = (a[0].x + a[1].x) + (a[2].x + a[3].x);
        float sx1 = (a[4].x + a[5].x) + (a[6].x + a[7].x);
        float sy0 = (a[0].y + a[1].y) + (a[2].y + a[3].y);
        float sy1 = (a[4].y + a[5].y) + (a[6].y + a[7].y);
        acc.x += sx0 + sx1;
        acc.y += sy0 + sy1;
        j = jn;
        have = haven;
#pragma unroll
        for (int k = 0; k < 8; k++) s[k] = sn[k];
    }
    for (; j + 2 <= end; j += 2) {
        int s0 = g_colidx[j], s1 = g_colidx[j + 1];
        float2 a0 = h2[(size_t)s0 * 32 + l];
        float2 a1 = h2[(size_t)s1 * 32 + l];
        acc.x += a0.x + a1.x;
        acc.y += a0.y + a1.y;
    }
    if (j < end) {
        int ss = g_colidx[j];
        float2 a = h2[(size_t)ss * 32 + l];
        acc.x += a.x; acc.y += a.y;
    }
    float2 bv = ((const float2*)b)[l];
    float2 r;
    r.x = acc.x * dvw + bv.x;
    r.y = acc.y * dvw + bv.y;
    ((float2*)g_x)[(size_t)w * 32 + l] = r;
}

// ---------------------------------------------------------------------------
// BN column reduction + last-block scale/shift (proven)
// ---------------------------------------------------------------------------
__global__ void __launch_bounds__(256) k_bnred(const float* __restrict__ gamma,
                                               const float* __restrict__ beta) {
    int d  = threadIdx.x & 63;
    int r0 = blockIdx.x * 4 + (threadIdx.x >> 6);
    int rs = gridDim.x * 4;
    float s = 0.f, q = 0.f;
    for (int n = r0; n < NNODES; n += rs) {
        float v = g_x[(size_t)n * 64 + d];
        s += v;
        q += v * v;
    }
    __shared__ double ss[256], sq[256];
    ss[threadIdx.x] = (double)s;
    sq[threadIdx.x] = (double)q;
    __syncthreads();
    if (threadIdx.x < 64) {
        double sd = ss[threadIdx.x] + ss[threadIdx.x + 64] + ss[threadIdx.x + 128] + ss[threadIdx.x + 192];
        double qd = sq[threadIdx.x] + sq[threadIdx.x + 64] + sq[threadIdx.x + 128] + sq[threadIdx.x + 192];
        atomicAdd(&g_sum[d], sd);
        atomicAdd(&g_sumsq[d], qd);
    }
    __shared__ int s_last;
    __threadfence();
    __syncthreads();
    if (threadIdx.x == 0) {
        int t = atomicAdd(&g_bnticket, 1);
        s_last = (t == gridDim.x - 1) ? 1 : 0;
    }
    __syncthreads();
    if (s_last && threadIdx.x < 64) {
        int dd = threadIdx.x;
        double mean = g_sum[dd] / (double)NNODES;
        double var  = g_sumsq[dd] / (double)NNODES - mean * mean;
        double inv  = 1.0 / sqrt(var + 1e-5);
        double sc   = (double)gamma[dd] * inv;
        g_scale[dd] = (float)sc;
        g_shift[dd] = (float)((double)beta[dd] - mean * sc);
    }
}

__global__ void __launch_bounds__(256) k_fin(float* __restrict__ out) {
    int i = blockIdx.x * blockDim.x + threadIdx.x;
    if (i >= NNODES * 16) return;
    float4 v = ((const float4*)g_x)[i];
    int d = (i & 15) * 4;
    v.x = v.x * g_scale[d + 0] + g_shift[d + 0];
    v.y = v.y * g_scale[d + 1] + g_shift[d + 1];
    v.z = v.z * g_scale[d + 2] + g_shift[d + 2];
    v.w = v.w * g_scale[d + 3] + g_shift[d + 3];
    ((float4*)out)[i] = v;
}

// ---------------------------------------------------------------------------
// Launch
// ---------------------------------------------------------------------------
extern "C" void kernel_launch(void* const* d_in, const int* in_sizes, int n_in,
                              void* d_out, int out_size) {
    const float* x     = (const float*)d_in[0];
    const void*  ei    = d_in[1];
    const float* Ws    = (const float*)d_in[2];
    const float* bs    = (const float*)d_in[3];
    const float* gamma = (const float*)d_in[4];
    const float* beta  = (const float*)d_in[5];
    float* out = (float*)d_out;

    int agg_blocks = (NNODES * 32) / 256;  // 12500, exact

    k_init<<<(NNODES + 255) / 256, 256>>>((const int*)ei);
    k_hist<<<HIST_BLOCKS, 256>>>(ei);
    k_scan1<<<SB, 256>>>();
    k_scan3<<<SB, 256>>>();
    k_fused2<<<GEMM_BLOCKS + FILL_BLOCKS, 256>>>(x, Ws, ei);

    k_agg<<<agg_blocks, 256>>>(bs);

    k_gemm_s<<<GEMM_BLOCKS, 256>>>(Ws + 1 * 64 * 64);
    k_agg<<<agg_blocks, 256>>>(bs + 1 * 64);

    k_gemm_s<<<GEMM_BLOCKS, 256>>>(Ws + 2 * 64 * 64);
    k_agg<<<agg_blocks, 256>>>(bs + 2 * 64);

    k_bnred<<<BNRED_BLOCKS, 256>>>(gamma, beta);
    k_fin<<<(NNODES * 16 + 255) / 256, 256>>>(out);
}

// round 17
// speedup vs baseline: 1.2417x; 1.1140x over previous
#include <cuda_runtime.h>

// Problem constants
constexpr int NNODES = 100000;
constexpr int D      = 64;
constexpr int NE     = 1250000;
constexpr int SB     = (NNODES + 1023) / 1024;  // 98 scan blocks
constexpr int GEMM_BLOCKS = (NNODES + 127) / 128;  // 782
constexpr int FILL_BLOCKS = 1266;                  // 782+1266 = 2048 grid
constexpr int HIST_BLOCKS = 2048;
constexpr int BNRED_BLOCKS = 512;

// ---------------------------------------------------------------------------
// Device scratch
// ---------------------------------------------------------------------------
__device__ float  g_h[NNODES * D];
__device__ float  g_x[NNODES * D];
__device__ float  g_dis[NNODES];
__device__ int    g_cnt[NNODES];
__device__ int    g_rowptr[NNODES + 1];
__device__ int    g_cursor[NNODES];
__device__ int    g_colidx[NE];
__device__ int    g_blocksum[SB];
__device__ double g_sum[D];
__device__ double g_sumsq[D];
__device__ float  g_scale[D];
__device__ float  g_shift[D];
__device__ int    g_is64;
__device__ int    g_bnticket;

// ---------------------------------------------------------------------------
// 0. init
// ---------------------------------------------------------------------------
__global__ void k_init(const int* __restrict__ e) {
    int i = blockIdx.x * blockDim.x + threadIdx.x;
    if (i < NNODES) g_cnt[i] = 0;
    if (i < D) { g_sum[i] = 0.0; g_sumsq[i] = 0.0; }
    if (i == 0) g_bnticket = 0;
    if (blockIdx.x == 0) {
        __shared__ int s_nz;
        if (threadIdx.x == 0) s_nz = 0;
        __syncthreads();
        int nz = 0;
        for (int j = threadIdx.x; j < 2048; j += blockDim.x)
            nz |= (e[2 * j + 1] != 0);
        if (nz) atomicOr(&s_nz, 1);
        __syncthreads();
        if (threadIdx.x == 0) g_is64 = (s_nz == 0) ? 1 : 0;
    }
}

// ---------------------------------------------------------------------------
// Histogram of dst (standalone; vectorized 2 edges/iter)
// ---------------------------------------------------------------------------
__global__ void __launch_bounds__(256) k_hist(const void* __restrict__ ep) {
    int i0 = blockIdx.x * 256 + threadIdx.x;
    int stride = HIST_BLOCKS * 256;
    if (g_is64) {
        const longlong2* d2 = (const longlong2*)((const long long*)ep + NE);
        for (int i = i0; i < NE / 2; i += stride) {
            longlong2 v = d2[i];
            atomicAdd(&g_cnt[(int)v.x], 1);
            atomicAdd(&g_cnt[(int)v.y], 1);
        }
    } else {
        const int2* d2 = (const int2*)((const int*)ep + NE);
        for (int i = i0; i < NE / 2; i += stride) {
            int2 v = d2[i];
            atomicAdd(&g_cnt[v.x], 1);
            atomicAdd(&g_cnt[v.y], 1);
        }
    }
}

// ---------------------------------------------------------------------------
// GEMM body (FFMA2 / fma.rn.f32x2): g_h[n] = dis[n] * (X[n] @ W^T)
// ---------------------------------------------------------------------------
__device__ __forceinline__ void gemm_body(const float* __restrict__ X,
                                          const float* __restrict__ W,
                                          int bid) {
    // sx2[r*32 + ((kp + r) & 31)] = (x[r][2kp], x[r][2kp+1])
    __shared__ float2 sx2[128 * 32];
    // sw2[kp*64 + j*8 + tc] = (W[tc*8+j][2kp], W[tc*8+j][2kp+1])
    __shared__ float2 sw2[32 * 64];
    int tid = threadIdx.x;

    const float2* W2 = (const float2*)W;   // W2[d*32+kp]
    for (int i = tid; i < 2048; i += 256) {
        int kp = i >> 6, t6 = i & 63;
        int j = t6 >> 3, tcc = t6 & 7;
        int d = tcc * 8 + j;
        sw2[i] = W2[d * 32 + kp];
    }
    int n0 = bid * 128;
    const float4* X4 = (const float4*)X;
    for (int i = tid; i < 2048; i += 256) {
        int r = i >> 4, c = i & 15;
        int n = n0 + r;
        float4 v = (n < NNODES) ? X4[(size_t)n * 16 + c]
                                : make_float4(0.f, 0.f, 0.f, 0.f);
        sx2[r * 32 + ((2 * c + r) & 31)]     = make_float2(v.x, v.y);
        sx2[r * 32 + ((2 * c + 1 + r) & 31)] = make_float2(v.z, v.w);
    }
    __syncthreads();

    int tc = tid & 7, tr = tid >> 3;
    int nb = tr * 4;
    unsigned long long acc[4][8];
#pragma unroll
    for (int i = 0; i < 4; i++)
#pragma unroll
        for (int j = 0; j < 8; j++) acc[i][j] = 0ull;

#pragma unroll 4
    for (int kp = 0; kp < 32; kp++) {
        unsigned long long wv[8];
#pragma unroll
        for (int j = 0; j < 8; j++)
            wv[j] = *(const unsigned long long*)&sw2[kp * 64 + j * 8 + tc];
        unsigned long long xv[4];
#pragma unroll
        for (int i = 0; i < 4; i++) {
            int n = nb + i;
            xv[i] = *(const unsigned long long*)&sx2[n * 32 + ((kp + n) & 31)];
        }
#pragma unroll
        for (int i = 0; i < 4; i++)
#pragma unroll
            for (int j = 0; j < 8; j++)
                asm("fma.rn.f32x2 %0, %1, %2, %0;"
                    : "+l"(acc[i][j]) : "l"(xv[i]), "l"(wv[j]));
    }

#pragma unroll
    for (int i = 0; i < 4; i++) {
        int n = n0 + nb + i;
        if (n < NNODES) {
            float dv = g_dis[n];
            float o[8];
#pragma unroll
            for (int j = 0; j < 8; j++) {
                unsigned long long a = acc[i][j];
                float lo = __uint_as_float((unsigned)(a & 0xffffffffull));
                float hi = __uint_as_float((unsigned)(a >> 32));
                o[j] = (lo + hi) * dv;
            }
            *(float4*)&g_h[(size_t)n * 64 + tc * 8]     = make_float4(o[0], o[1], o[2], o[3]);
            *(float4*)&g_h[(size_t)n * 64 + tc * 8 + 4] = make_float4(o[4], o[5], o[6], o[7]);
        }
    }
}

// CSR fill body (vectorized 2 edges/iter)
__device__ __forceinline__ void fill_body(const void* __restrict__ ep, int fb) {
    int i0 = fb * 256 + threadIdx.x;
    int stride = FILL_BLOCKS * 256;
    if (g_is64) {
        const longlong2* s2 = (const longlong2*)ep;
        const longlong2* d2 = (const longlong2*)((const long long*)ep + NE);
        for (int i = i0; i < NE / 2; i += stride) {
            longlong2 sv = s2[i];
            longlong2 dv = d2[i];
            int p0 = atomicAdd(&g_cursor[(int)dv.x], 1);
            g_colidx[p0] = (int)sv.x;
            int p1 = atomicAdd(&g_cursor[(int)dv.y], 1);
            g_colidx[p1] = (int)sv.y;
        }
    } else {
        const int2* s2 = (const int2*)ep;
        const int2* d2 = (const int2*)((const int*)ep + NE);
        for (int i = i0; i < NE / 2; i += stride) {
            int2 sv = s2[i];
            int2 dv = d2[i];
            int p0 = atomicAdd(&g_cursor[dv.x], 1);
            g_colidx[p0] = sv.x;
            int p1 = atomicAdd(&g_cursor[dv.y], 1);
            g_colidx[p1] = sv.y;
        }
    }
}

// fused: layer-1 GEMM (dis-scaled; runs after scan) || CSR fill
__global__ void __launch_bounds__(256) k_fused2(const float* __restrict__ X,
                                                 const float* __restrict__ W,
                                                 const void* __restrict__ ep) {
    if (blockIdx.x < GEMM_BLOCKS) gemm_body(X, W, blockIdx.x);
    else                          fill_body(ep, blockIdx.x - GEMM_BLOCKS);
}

__global__ void __launch_bounds__(256) k_gemm_s(const float* __restrict__ W) {
    gemm_body(g_x, W, blockIdx.x);
}

// ---------------------------------------------------------------------------
// Parallel scan (2 kernels; proven)
// ---------------------------------------------------------------------------
__global__ void __launch_bounds__(256) k_scan1() {
    __shared__ int warpsum[8];
    int b = blockIdx.x, t = threadIdx.x;
    int base = b * 1024 + t * 4;
    int c[4]; int s = 0;
#pragma unroll
    for (int i = 0; i < 4; i++) {
        int idx = base + i;
        c[i] = (idx < NNODES) ? g_cnt[idx] : 0;
        s += c[i];
    }
    int lane = t & 31, w = t >> 5;
    int v = s;
#pragma unroll
    for (int off = 1; off < 32; off <<= 1) {
        int u = __shfl_up_sync(~0u, v, off);
        if (lane >= off) v += u;
    }
    if (lane == 31) warpsum[w] = v;
    __syncthreads();
    if (t < 8) {
        int u = warpsum[t];
#pragma unroll
        for (int off = 1; off < 8; off <<= 1) {
            int uu = __shfl_up_sync(0xffu, u, off);
            if (t >= off) u += uu;
        }
        warpsum[t] = u;
    }
    __syncthreads();
    int run = v - s + (w > 0 ? warpsum[w - 1] : 0);
#pragma unroll
    for (int i = 0; i < 4; i++) {
        int idx = base + i;
        if (idx < NNODES) g_rowptr[idx] = run;
        run += c[i];
    }
    if (t == 255) g_blocksum[b] = warpsum[7];
}

__global__ void __launch_bounds__(256) k_scan3() {
    __shared__ int red[256];
    int b = blockIdx.x, t = threadIdx.x;
    int bsv = (t < SB) ? g_blocksum[t] : 0;
    red[t] = (t < b) ? bsv : 0;
    __syncthreads();
    for (int off = 128; off > 0; off >>= 1) {
        if (t < off) red[t] += red[t + off];
        __syncthreads();
    }
    int off0 = red[0];
    if (b == SB - 1 && t == 0) g_rowptr[NNODES] = off0 + g_blocksum[SB - 1];
    int base = b * 1024 + t * 4;
#pragma unroll
    for (int i = 0; i < 4; i++) {
        int idx = base + i;
        if (idx < NNODES) {
            int r = g_rowptr[idx] + off0;
            g_rowptr[idx] = r;
            g_cursor[idx] = r;
            g_dis[idx] = rsqrtf((float)(g_cnt[idx] + 1));
        }
    }
}

// ---------------------------------------------------------------------------
// Aggregation: warp per node, lane l owns float2 at dim 2l. Unroll 8 for MLP.
// ---------------------------------------------------------------------------
__global__ void __launch_bounds__(256) k_agg(const float* __restrict__ b) {
    int w = (blockIdx.x * blockDim.x + threadIdx.x) >> 5;
    int l = threadIdx.x & 31;
    if (w >= NNODES) return;
    const float2* __restrict__ h2 = (const float2*)g_h;
    float dvw = g_dis[w];
    float2 acc = h2[(size_t)w * 32 + l];
    int beg = g_rowptr[w];
    int end = g_rowptr[w + 1];
    int j = beg;
    for (; j + 8 <= end; j += 8) {
        int s[8];
#pragma unroll
        for (int k = 0; k < 8; k++) s[k] = g_colidx[j + k];
        float2 a[8];
#pragma unroll
        for (int k = 0; k < 8; k++) a[k] = h2[(size_t)s[k] * 32 + l];
        float sx0 = (a[0].x + a[1].x) + (a[2].x + a[3].x);
        float sx1 = (a[4].x + a[5].x) + (a[6].x + a[7].x);
        float sy0 = (a[0].y + a[1].y) + (a[2].y + a[3].y);
        float sy1 = (a[4].y + a[5].y) + (a[6].y + a[7].y);
        acc.x += sx0 + sx1;
        acc.y += sy0 + sy1;
    }
    for (; j + 2 <= end; j += 2) {
        int s0 = g_colidx[j], s1 = g_colidx[j + 1];
        float2 a0 = h2[(size_t)s0 * 32 + l];
        float2 a1 = h2[(size_t)s1 * 32 + l];
        acc.x += a0.x + a1.x;
        acc.y += a0.y + a1.y;
    }
    if (j < end) {
        int s = g_colidx[j];
        float2 a = h2[(size_t)s * 32 + l];
        acc.x += a.x; acc.y += a.y;
    }
    float2 bv = ((const float2*)b)[l];
    float2 r;
    r.x = acc.x * dvw + bv.x;
    r.y = acc.y * dvw + bv.y;
    ((float2*)g_x)[(size_t)w * 32 + l] = r;
}

// ---------------------------------------------------------------------------
// BN column reduction + last-block scale/shift (proven)
// ---------------------------------------------------------------------------
__global__ void __launch_bounds__(256) k_bnred(const float* __restrict__ gamma,
                                               const float* __restrict__ beta) {
    int d  = threadIdx.x & 63;
    int r0 = blockIdx.x * 4 + (threadIdx.x >> 6);
    int rs = gridDim.x * 4;
    float s = 0.f, q = 0.f;
    for (int n = r0; n < NNODES; n += rs) {
        float v = g_x[(size_t)n * 64 + d];
        s += v;
        q += v * v;
    }
    __shared__ double ss[256], sq[256];
    ss[threadIdx.x] = (double)s;
    sq[threadIdx.x] = (double)q;
    __syncthreads();
    if (threadIdx.x < 64) {
        double sd = ss[threadIdx.x] + ss[threadIdx.x + 64] + ss[threadIdx.x + 128] + ss[threadIdx.x + 192];
        double qd = sq[threadIdx.x] + sq[threadIdx.x + 64] + sq[threadIdx.x + 128] + sq[threadIdx.x + 192];
        atomicAdd(&g_sum[d], sd);
        atomicAdd(&g_sumsq[d], qd);
    }
    __shared__ int s_last;
    __threadfence();
    __syncthreads();
    if (threadIdx.x == 0) {
        int t = atomicAdd(&g_bnticket, 1);
        s_last = (t == gridDim.x - 1) ? 1 : 0;
    }
    __syncthreads();
    if (s_last && threadIdx.x < 64) {
        int dd = threadIdx.x;
        double mean = g_sum[dd] / (double)NNODES;
        double var  = g_sumsq[dd] / (double)NNODES - mean * mean;
        double inv  = 1.0 / sqrt(var + 1e-5);
        double sc   = (double)gamma[dd] * inv;
        g_scale[dd] = (float)sc;
        g_shift[dd] = (float)((double)beta[dd] - mean * sc);
    }
}

__global__ void __launch_bounds__(256) k_fin(float* __restrict__ out) {
    int i = blockIdx.x * blockDim.x + threadIdx.x;
    if (i >= NNODES * 16) return;
    float4 v = ((const float4*)g_x)[i];
    int d = (i & 15) * 4;
    v.x = v.x * g_scale[d + 0] + g_shift[d + 0];
    v.y = v.y * g_scale[d + 1] + g_shift[d + 1];
    v.z = v.z * g_scale[d + 2] + g_shift[d + 2];
    v.w = v.w * g_scale[d + 3] + g_shift[d + 3];
    ((float4*)out)[i] = v;
}

// ---------------------------------------------------------------------------
// Launch
// ---------------------------------------------------------------------------
extern "C" void kernel_launch(void* const* d_in, const int* in_sizes, int n_in,
                              void* d_out, int out_size) {
    const float* x     = (const float*)d_in[0];
    const void*  ei    = d_in[1];
    const float* Ws    = (const float*)d_in[2];
    const float* bs    = (const float*)d_in[3];
    const float* gamma = (const float*)d_in[4];
    const float* beta  = (const float*)d_in[5];
    float* out = (float*)d_out;

    int agg_blocks = (NNODES * 32) / 256;  // 12500, exact

    k_init<<<(NNODES + 255) / 256, 256>>>((const int*)ei);
    k_hist<<<HIST_BLOCKS, 256>>>(ei);
    k_scan1<<<SB, 256>>>();
    k_scan3<<<SB, 256>>>();
    // layer-1 GEMM (dis-scaled, needs scan) overlapped with CSR fill
    k_fused2<<<GEMM_BLOCKS + FILL_BLOCKS, 256>>>(x, Ws, ei);

    k_agg<<<agg_blocks, 256>>>(bs);

    k_gemm_s<<<GEMM_BLOCKS, 256>>>(Ws + 1 * 64 * 64);
    k_agg<<<agg_blocks, 256>>>(bs + 1 * 64);

    k_gemm_s<<<GEMM_BLOCKS, 256>>>(Ws + 2 * 64 * 64);
    k_agg<<<agg_blocks, 256>>>(bs + 2 * 64);

    k_bnred<<<BNRED_BLOCKS, 256>>>(gamma, beta);
    k_fin<<<(NNODES * 16 + 255) / 256, 256>>>(out);
}